// round 5
// baseline (speedup 1.0000x reference)
#include <cuda_runtime.h>

// NCA fused step, fp32 scalar-FFMA version.
// grid[32,16,256,256] -> perception(48) -> w1(128x48)+relu -> w2(16x128)
// -> masked residual -> clip(-2,2).
// One thread per pixel; weights staged in SMEM (broadcast LDS.128 reads).

#define TC   16      // total channels
#define HID  128     // hidden units
#define PCH  48      // perception channels (3 * TC)
#define IMH  256
#define IMW  256
#define NB   32      // batch

__global__ __launch_bounds__(256, 2)
void nca_fused_kernel(const float* __restrict__ grid,
                      const float* __restrict__ noise,
                      const float* __restrict__ w1,
                      const float* __restrict__ b1,
                      const float* __restrict__ w2,
                      const float* __restrict__ b2,
                      float* __restrict__ out)
{
    __shared__ float w1s[HID * PCH];   // 24 KB, row-major [o][p]
    __shared__ float w2ts[HID * TC];   // 8 KB, transposed [o][c]
    __shared__ float b1s[HID];
    __shared__ float b2s[TC];

    const int tid = threadIdx.y * 32 + threadIdx.x;

    // Stage weights (one-time per block, tiny vs compute).
    for (int i = tid; i < HID * PCH; i += 256) w1s[i] = w1[i];
    for (int i = tid; i < HID * TC; i += 256) {
        int o = i >> 4, c = i & 15;
        w2ts[i] = w2[c * HID + o];     // transpose: w2 is [TC][HID]
    }
    if (tid < HID) b1s[tid] = b1[tid];
    if (tid < TC)  b2s[tid] = b2[tid];
    __syncthreads();

    const int b = blockIdx.z;
    const int x = blockIdx.x * 32 + threadIdx.x;
    const int y = blockIdx.y * 8 + threadIdx.y;
    const int pix = y * IMW + x;

    const bool ym = (y > 0), yp = (y < IMH - 1);
    const bool xm = (x > 0), xp = (x < IMW - 1);

    const float* gb = grid + (size_t)b * TC * IMH * IMW;

    // Perception: identity + sobel_x-as-written + sobel_y, zero padding,
    // cross-correlation (XLA conv semantics). Order: [c_id, c_sx, c_sy] per c.
    float perc[PCH];
    #pragma unroll
    for (int c = 0; c < TC; c++) {
        const float* g = gb + c * (IMH * IMW) + pix;
        float n00 = (ym && xm) ? __ldg(g - IMW - 1) : 0.f;
        float n01 = (ym)       ? __ldg(g - IMW)     : 0.f;
        float n02 = (ym && xp) ? __ldg(g - IMW + 1) : 0.f;
        float n10 = (xm)       ? __ldg(g - 1)       : 0.f;
        float n11 =              __ldg(g);
        float n12 = (xp)       ? __ldg(g + 1)       : 0.f;
        float n20 = (yp && xm) ? __ldg(g + IMW - 1) : 0.f;
        float n21 = (yp)       ? __ldg(g + IMW)     : 0.f;
        float n22 = (yp && xp) ? __ldg(g + IMW + 1) : 0.f;
        perc[3*c]     = n11;
        // sobel_x faithful to reference: [[1,0,1],[2,0,-2],[1,0,-1]]/8
        perc[3*c + 1] = (n00 + n02 + 2.f*n10 - 2.f*n12 + n20 - n22) * 0.125f;
        // sobel_y: [[1,2,1],[0,0,0],[-1,-2,-1]]/8
        perc[3*c + 2] = (n00 + 2.f*n01 + n02 - n20 - 2.f*n21 - n22) * 0.125f;
    }

    float acc[TC];
    #pragma unroll
    for (int c = 0; c < TC; c++) acc[c] = b2s[c];

    // Hidden loop: h_o = relu(b1[o] + w1[o,:]·perc); acc += w2t[o,:] * h_o.
    // 4 partial sums break the FMA dependency chain; wr[p..p+3] -> LDS.128
    // broadcast (uniform address across the warp, conflict-free).
    #pragma unroll 2
    for (int o = 0; o < HID; o++) {
        const float* wr = w1s + o * PCH;
        float h0 = b1s[o], h1 = 0.f, h2 = 0.f, h3 = 0.f;
        #pragma unroll
        for (int p = 0; p < PCH; p += 4) {
            h0 = fmaf(wr[p],     perc[p],     h0);
            h1 = fmaf(wr[p + 1], perc[p + 1], h1);
            h2 = fmaf(wr[p + 2], perc[p + 2], h2);
            h3 = fmaf(wr[p + 3], perc[p + 3], h3);
        }
        float hh = fmaxf((h0 + h1) + (h2 + h3), 0.f);
        const float* w2r = w2ts + o * TC;
        #pragma unroll
        for (int c = 0; c < TC; c++) acc[c] = fmaf(w2r[c], hh, acc[c]);
    }

    // Stochastic mask (broadcast over channels) + residual + clip.
    const float nz = __ldg(noise + (size_t)b * IMH * IMW + pix);
    const float m = (nz < 0.5f) ? 1.f : 0.f;

    float* ob = out + (size_t)b * TC * IMH * IMW + pix;
    #pragma unroll
    for (int c = 0; c < TC; c++) {
        float v = fmaf(acc[c], m, perc[3*c]);   // perc[3c] == grid center value
        v = fminf(fmaxf(v, -2.f), 2.f);
        ob[c * (IMH * IMW)] = v;
    }
}

extern "C" void kernel_launch(void* const* d_in, const int* in_sizes, int n_in,
                              void* d_out, int out_size)
{
    const float* grid  = (const float*)d_in[0];
    const float* noise = (const float*)d_in[1];
    const float* w1    = (const float*)d_in[2];
    const float* b1    = (const float*)d_in[3];
    const float* w2    = (const float*)d_in[4];
    const float* b2    = (const float*)d_in[5];
    float* out = (float*)d_out;

    dim3 block(32, 8, 1);
    dim3 grd(IMW / 32, IMH / 8, NB);
    nca_fused_kernel<<<grd, block>>>(grid, noise, w1, b1, w2, b2, out);
}

// round 6
// speedup vs baseline: 1.0571x; 1.0571x over previous
#include <cuda_runtime.h>

// NCA fused step — packed fp32x2 (fma.rn.f32x2) version.
// grid[32,16,256,256] -> perception(48) -> w1(128x48)+relu -> w2(16x128)
// -> masked residual -> clip(-2,2).
// One thread per pixel; perception + accumulators packed as f32x2 pairs so the
// MLP runs on the 2-wide fp32 path (FFMA2), which ptxas never emits from C++.

#define TC   16
#define HID  128
#define PCH  48
#define IMH  256
#define IMW  256
#define NB   32

typedef unsigned long long ull;

#define FMA2(d, a, b, c) \
    asm("fma.rn.f32x2 %0, %1, %2, %3;" : "=l"(d) : "l"(a), "l"(b), "l"(c))
#define ADD2(d, a, b) \
    asm("add.rn.f32x2 %0, %1, %2;" : "=l"(d) : "l"(a), "l"(b))
#define PACK2(d, lo, hi) \
    asm("mov.b64 %0, {%1, %2};" : "=l"(d) : "f"(lo), "f"(hi))
#define UNPACK2(lo, hi, s) \
    asm("mov.b64 {%0, %1}, %2;" : "=f"(lo), "=f"(hi) : "l"(s))

__global__ __launch_bounds__(256, 2)
void nca_fused_kernel(const float* __restrict__ grid,
                      const float* __restrict__ noise,
                      const float* __restrict__ w1,
                      const float* __restrict__ b1,
                      const float* __restrict__ w2,
                      const float* __restrict__ b2,
                      float* __restrict__ out)
{
    __shared__ __align__(16) float w1s[HID * PCH];   // 24 KB, row-major [o][p]
    __shared__ __align__(16) float w2ts[HID * TC];   // 8 KB, transposed [o][c]
    __shared__ float b1s[HID];
    __shared__ float b2s[TC];

    const int tid = threadIdx.y * 32 + threadIdx.x;

    for (int i = tid; i < HID * PCH; i += 256) w1s[i] = w1[i];
    for (int i = tid; i < HID * TC; i += 256) {
        int o = i >> 4, c = i & 15;
        w2ts[i] = w2[c * HID + o];     // transpose: w2 is [TC][HID]
    }
    if (tid < HID) b1s[tid] = b1[tid];
    if (tid < TC)  b2s[tid] = b2[tid];
    __syncthreads();

    const int b = blockIdx.z;
    const int x = blockIdx.x * 32 + threadIdx.x;
    const int y = blockIdx.y * 8 + threadIdx.y;
    const int pix = y * IMW + x;

    const bool ym = (y > 0), yp = (y < IMH - 1);
    const bool xm = (x > 0), xp = (x < IMW - 1);

    const float* gb = grid + (size_t)b * TC * IMH * IMW;

    // Perception packed as f32x2 pairs over p: pp[j] = (perc[2j], perc[2j+1]).
    // Per channel c: perc[3c]=identity, perc[3c+1]=sobel_x(as written),
    // perc[3c+2]=sobel_y. Zero padding, cross-correlation (XLA semantics).
    ull pp[PCH / 2];
    #pragma unroll
    for (int c = 0; c < TC; c += 2) {
        float v[6];
        #pragma unroll
        for (int k = 0; k < 2; k++) {
            const float* g = gb + (c + k) * (IMH * IMW) + pix;
            float n00 = (ym && xm) ? __ldg(g - IMW - 1) : 0.f;
            float n01 = (ym)       ? __ldg(g - IMW)     : 0.f;
            float n02 = (ym && xp) ? __ldg(g - IMW + 1) : 0.f;
            float n10 = (xm)       ? __ldg(g - 1)       : 0.f;
            float n11 =              __ldg(g);
            float n12 = (xp)       ? __ldg(g + 1)       : 0.f;
            float n20 = (yp && xm) ? __ldg(g + IMW - 1) : 0.f;
            float n21 = (yp)       ? __ldg(g + IMW)     : 0.f;
            float n22 = (yp && xp) ? __ldg(g + IMW + 1) : 0.f;
            v[3*k]     = n11;
            // sobel_x faithful to reference: [[1,0,1],[2,0,-2],[1,0,-1]]/8
            v[3*k + 1] = (n00 + n02 + 2.f*n10 - 2.f*n12 + n20 - n22) * 0.125f;
            // sobel_y: [[1,2,1],[0,0,0],[-1,-2,-1]]/8
            v[3*k + 2] = (n00 + 2.f*n01 + n02 - n20 - 2.f*n21 - n22) * 0.125f;
        }
        const int q = (3 * c) >> 1;   // 3c is even (c even)
        PACK2(pp[q],     v[0], v[1]);
        PACK2(pp[q + 1], v[2], v[3]);
        PACK2(pp[q + 2], v[4], v[5]);
    }

    // Packed output accumulators over channel pairs: accp[k] = (b2[2k], b2[2k+1]).
    ull accp[TC / 2];
    #pragma unroll
    for (int k = 0; k < TC / 2; k++) PACK2(accp[k], b2s[2*k], b2s[2*k + 1]);

    // Hidden loop: h_o = relu(b1[o] + w1[o,:]·perc); accp += w2t[o,:] * (h_o,h_o).
    // w1 row read as LDS.128 (2 packed pairs per load, warp-uniform broadcast).
    #pragma unroll 2
    for (int o = 0; o < HID; o++) {
        const ulonglong2* wr = (const ulonglong2*)(w1s + o * PCH);
        ull h0, h1, h2, h3;
        {
            ulonglong2 w = wr[0];
            asm("mul.rn.f32x2 %0, %1, %2;" : "=l"(h0) : "l"(w.x), "l"(pp[0]));
            asm("mul.rn.f32x2 %0, %1, %2;" : "=l"(h1) : "l"(w.y), "l"(pp[1]));
        }
        {
            ulonglong2 w = wr[1];
            asm("mul.rn.f32x2 %0, %1, %2;" : "=l"(h2) : "l"(w.x), "l"(pp[2]));
            asm("mul.rn.f32x2 %0, %1, %2;" : "=l"(h3) : "l"(w.y), "l"(pp[3]));
        }
        #pragma unroll
        for (int j = 2; j < 12; j += 2) {
            ulonglong2 wa = wr[j];
            ulonglong2 wb = wr[j + 1];
            FMA2(h0, wa.x, pp[2*j],     h0);
            FMA2(h1, wa.y, pp[2*j + 1], h1);
            FMA2(h2, wb.x, pp[2*j + 2], h2);
            FMA2(h3, wb.y, pp[2*j + 3], h3);
        }
        ADD2(h0, h0, h1);
        ADD2(h2, h2, h3);
        ADD2(h0, h0, h2);
        float lo, hi;
        UNPACK2(lo, hi, h0);
        float hh = fmaxf((lo + hi) + b1s[o], 0.f);
        ull hd;
        PACK2(hd, hh, hh);

        const ulonglong2* w2r = (const ulonglong2*)(w2ts + o * TC);
        #pragma unroll
        for (int j = 0; j < 4; j++) {
            ulonglong2 w = w2r[j];
            FMA2(accp[2*j],     w.x, hd, accp[2*j]);
            FMA2(accp[2*j + 1], w.y, hd, accp[2*j + 1]);
        }
    }

    // Stochastic mask (broadcast over channels) + residual + clip.
    const float nz = __ldg(noise + (size_t)b * IMH * IMW + pix);
    const float m = (nz < 0.5f) ? 1.f : 0.f;

    float* ob = out + (size_t)b * TC * IMH * IMW + pix;
    #pragma unroll
    for (int c = 0; c < TC; c++) {
        float alo, ahi;
        UNPACK2(alo, ahi, accp[c >> 1]);
        float upd = (c & 1) ? ahi : alo;
        // identity value for channel c lives at perc index 3c:
        // pair pp[(3c)>>1], lo half when 3c even (c even), hi half otherwise.
        float plo, phi;
        UNPACK2(plo, phi, pp[(3 * c) >> 1]);
        float idv = (c & 1) ? phi : plo;
        float v = fmaf(upd, m, idv);
        v = fminf(fmaxf(v, -2.f), 2.f);
        ob[c * (IMH * IMW)] = v;
    }
}

extern "C" void kernel_launch(void* const* d_in, const int* in_sizes, int n_in,
                              void* d_out, int out_size)
{
    const float* grid  = (const float*)d_in[0];
    const float* noise = (const float*)d_in[1];
    const float* w1    = (const float*)d_in[2];
    const float* b1    = (const float*)d_in[3];
    const float* w2    = (const float*)d_in[4];
    const float* b2    = (const float*)d_in[5];
    float* out = (float*)d_out;

    dim3 block(32, 8, 1);
    dim3 grd(IMW / 32, IMH / 8, NB);
    nca_fused_kernel<<<grd, block>>>(grid, noise, w1, b1, w2, b2, out);
}

// round 9
// speedup vs baseline: 1.6724x; 1.5821x over previous
#include <cuda_runtime.h>
#include <cstdint>

// NCA fused step via warp-level tensor-core MMA (mma.sync m16n8k8 tf32).
// CTA = 256 threads = one image row (256 px). Perception staged to SMEM,
// then each warp runs GEMM1 [32px,48]x[48,128] and GEMM2 [32px,128]x[128,16]
// on tensor cores, with a register shuffle relayout (D-frag -> A-frag) and
// fused bias/ReLU between them. Exact-f32 residual + mask + clip epilogue.

#define TC   16
#define HID  128
#define PCH  48
#define IMH  256
#define IMW  256
#define HW   (IMH * IMW)

// SMEM layout in floats (padded strides 52/132 for conflict-free frag loads)
#define PERC_OFF 0              // [256][52]
#define W1_OFF   13312          // [128][52]  w1[hid][perc], tf32-rounded
#define W2_OFF   19968          // [16][132]  w2[out][hid],  tf32-rounded
#define B1_OFF   22080          // [128]
#define B2_OFF   22208          // [16]
#define SMEM_F   22224
#define SMEM_BYTES (SMEM_F * 4)

__device__ __forceinline__ uint32_t to_tf32(float f) {
    uint32_t r;
    asm("cvt.rna.tf32.f32 %0, %1;" : "=r"(r) : "f"(f));
    return r;
}

__device__ __forceinline__ void mma8(float* d, const uint32_t* a,
                                     uint32_t b0, uint32_t b1) {
    asm volatile(
        "mma.sync.aligned.m16n8k8.row.col.f32.tf32.tf32.f32 "
        "{%0,%1,%2,%3}, {%4,%5,%6,%7}, {%8,%9}, {%0,%1,%2,%3};"
        : "+f"(d[0]), "+f"(d[1]), "+f"(d[2]), "+f"(d[3])
        : "r"(a[0]), "r"(a[1]), "r"(a[2]), "r"(a[3]), "r"(b0), "r"(b1));
}

extern __shared__ float sm[];

__global__ __launch_bounds__(256, 2)
void nca_mma_kernel(const float* __restrict__ grid,
                    const float* __restrict__ noise,
                    const float* __restrict__ w1,
                    const float* __restrict__ b1,
                    const float* __restrict__ w2,
                    const float* __restrict__ b2,
                    float* __restrict__ out)
{
    const int tid = threadIdx.x;
    const int y = blockIdx.x;
    const int b = blockIdx.y;

    // ---- stage weights (tf32-rounded; biases exact) ----
    for (int i = tid; i < HID * PCH; i += 256) {
        int h = i / PCH, p = i - h * PCH;
        sm[W1_OFF + h * 52 + p] = __uint_as_float(to_tf32(w1[i]));
    }
    for (int i = tid; i < TC * HID; i += 256) {
        int o = i >> 7, h = i & 127;
        sm[W2_OFF + o * 132 + h] = __uint_as_float(to_tf32(w2[i]));
    }
    if (tid < HID) sm[B1_OFF + tid] = b1[tid];
    if (tid < TC)  sm[B2_OFF + tid] = b2[tid];

    // ---- perception: thread -> pixel (x = tid) ----
    {
        const int x = tid;
        const int pix = y * IMW + x;
        const bool ym = (y > 0), yp = (y < IMH - 1);
        const bool xm = (x > 0), xp = (x < IMW - 1);
        const float* gb = grid + (size_t)b * TC * HW;

        uint32_t pu[PCH];
        #pragma unroll
        for (int c = 0; c < TC; c++) {
            const float* g = gb + c * HW + pix;
            float n00 = (ym && xm) ? __ldg(g - IMW - 1) : 0.f;
            float n01 = (ym)       ? __ldg(g - IMW)     : 0.f;
            float n02 = (ym && xp) ? __ldg(g - IMW + 1) : 0.f;
            float n10 = (xm)       ? __ldg(g - 1)       : 0.f;
            float n11 =              __ldg(g);
            float n12 = (xp)       ? __ldg(g + 1)       : 0.f;
            float n20 = (yp && xm) ? __ldg(g + IMW - 1) : 0.f;
            float n21 = (yp)       ? __ldg(g + IMW)     : 0.f;
            float n22 = (yp && xp) ? __ldg(g + IMW + 1) : 0.f;
            // sobel_x faithful to reference: [[1,0,1],[2,0,-2],[1,0,-1]]/8
            float sx = (n00 + n02 + 2.f*n10 - 2.f*n12 + n20 - n22) * 0.125f;
            // sobel_y: [[1,2,1],[0,0,0],[-1,-2,-1]]/8
            float sy = (n00 + 2.f*n01 + n02 - n20 - 2.f*n21 - n22) * 0.125f;
            pu[3*c]     = to_tf32(n11);
            pu[3*c + 1] = to_tf32(sx);
            pu[3*c + 2] = to_tf32(sy);
        }
        float4* dst = (float4*)&sm[PERC_OFF + tid * 52];
        const float4* src = (const float4*)pu;
        #pragma unroll
        for (int j = 0; j < 12; j++) dst[j] = src[j];
    }
    __syncthreads();

    // ---- per-warp GEMMs on 32-pixel M tile ----
    const int l = tid & 31, wp = tid >> 5;
    const int g = l >> 2, cq = l & 3;
    const int P0 = wp * 32;

    // Cache A1 fragments: perc[32,48] -> 2 mtiles x 6 ktiles x 4 regs
    uint32_t pa[2][6][4];
    #pragma unroll
    for (int mt = 0; mt < 2; mt++)
        #pragma unroll
        for (int kt = 0; kt < 6; kt++) {
            int base = PERC_OFF + (P0 + 16*mt + g) * 52 + 8*kt + cq;
            pa[mt][kt][0] = __float_as_uint(sm[base]);
            pa[mt][kt][1] = __float_as_uint(sm[base + 8*52]);
            pa[mt][kt][2] = __float_as_uint(sm[base + 4]);
            pa[mt][kt][3] = __float_as_uint(sm[base + 8*52 + 4]);
        }

    float acc[2][2][4] = {};
    const unsigned sA = (l & ~3u) | ((unsigned)cq >> 1);
    const unsigned sB = sA + 2;
    const bool odd = cq & 1;

    #pragma unroll
    for (int n0 = 0; n0 < 4; n0++) {         // hid chunk of 32
        const int H0 = 32 * n0;
        float d[2][4][4] = {};
        // GEMM1: d[mt][nt] += perc x w1^T
        #pragma unroll
        for (int nt = 0; nt < 4; nt++) {
            #pragma unroll
            for (int kt = 0; kt < 6; kt++) {
                int ba = W1_OFF + (H0 + 8*nt + g) * 52 + 8*kt + cq;
                uint32_t wb0 = __float_as_uint(sm[ba]);
                uint32_t wb1 = __float_as_uint(sm[ba + 4]);
                mma8(d[0][nt], pa[0][kt], wb0, wb1);
                mma8(d[1][nt], pa[1][kt], wb0, wb1);
            }
        }
        // bias + relu + tf32, relayout D-frag -> A-frag, GEMM2 partial
        #pragma unroll
        for (int nt = 0; nt < 4; nt++) {
            float bs0 = sm[B1_OFF + H0 + 8*nt + 2*cq];
            float bs1 = sm[B1_OFF + H0 + 8*nt + 2*cq + 1];
            uint32_t w2b[2][2];
            #pragma unroll
            for (int nt2 = 0; nt2 < 2; nt2++) {
                int a2 = W2_OFF + (8*nt2 + g) * 132 + H0 + 8*nt + cq;
                w2b[nt2][0] = __float_as_uint(sm[a2]);
                w2b[nt2][1] = __float_as_uint(sm[a2 + 4]);
            }
            #pragma unroll
            for (int mt = 0; mt < 2; mt++) {
                uint32_t u0 = to_tf32(fmaxf(d[mt][nt][0] + bs0, 0.f));
                uint32_t u1 = to_tf32(fmaxf(d[mt][nt][1] + bs1, 0.f));
                uint32_t u2 = to_tf32(fmaxf(d[mt][nt][2] + bs0, 0.f));
                uint32_t u3 = to_tf32(fmaxf(d[mt][nt][3] + bs1, 0.f));
                // D cols {2c,2c+1} -> A cols {c, c+4}
                uint32_t t0A = __shfl_sync(0xffffffffu, u0, sA);
                uint32_t t1A = __shfl_sync(0xffffffffu, u1, sA);
                uint32_t t2A = __shfl_sync(0xffffffffu, u2, sA);
                uint32_t t3A = __shfl_sync(0xffffffffu, u3, sA);
                uint32_t t0B = __shfl_sync(0xffffffffu, u0, sB);
                uint32_t t1B = __shfl_sync(0xffffffffu, u1, sB);
                uint32_t t2B = __shfl_sync(0xffffffffu, u2, sB);
                uint32_t t3B = __shfl_sync(0xffffffffu, u3, sB);
                uint32_t a[4];
                a[0] = odd ? t1A : t0A;   // (row g,   col c)
                a[1] = odd ? t3A : t2A;   // (row g+8, col c)
                a[2] = odd ? t1B : t0B;   // (row g,   col c+4)
                a[3] = odd ? t3B : t2B;   // (row g+8, col c+4)
                mma8(acc[mt][0], a, w2b[0][0], w2b[0][1]);
                mma8(acc[mt][1], a, w2b[1][0], w2b[1][1]);
            }
        }
    }

    // ---- epilogue: +b2, mask, exact-f32 residual, clip, store ----
    const float* nb = noise + (size_t)b * HW + y * IMW;
    #pragma unroll
    for (int mt = 0; mt < 2; mt++) {
        const int r0 = P0 + 16*mt + g;
        const float m0 = (__ldg(nb + r0)     < 0.5f) ? 1.f : 0.f;
        const float m1 = (__ldg(nb + r0 + 8) < 0.5f) ? 1.f : 0.f;
        #pragma unroll
        for (int nt2 = 0; nt2 < 2; nt2++) {
            const int o0 = 8*nt2 + 2*cq;
            const float bv0 = sm[B2_OFF + o0];
            const float bv1 = sm[B2_OFF + o0 + 1];
            const float* gp0 = grid + ((size_t)b * TC + o0) * HW + y * IMW;
            const float* gp1 = gp0 + HW;
            float* op0 = out + ((size_t)b * TC + o0) * HW + y * IMW;
            float* op1 = op0 + HW;
            float v;
            v = fmaf(acc[mt][nt2][0] + bv0, m0, __ldg(gp0 + r0));
            op0[r0]     = fminf(fmaxf(v, -2.f), 2.f);
            v = fmaf(acc[mt][nt2][1] + bv1, m0, __ldg(gp1 + r0));
            op1[r0]     = fminf(fmaxf(v, -2.f), 2.f);
            v = fmaf(acc[mt][nt2][2] + bv0, m1, __ldg(gp0 + r0 + 8));
            op0[r0 + 8] = fminf(fmaxf(v, -2.f), 2.f);
            v = fmaf(acc[mt][nt2][3] + bv1, m1, __ldg(gp1 + r0 + 8));
            op1[r0 + 8] = fminf(fmaxf(v, -2.f), 2.f);
        }
    }
}

extern "C" void kernel_launch(void* const* d_in, const int* in_sizes, int n_in,
                              void* d_out, int out_size)
{
    const float* grid  = (const float*)d_in[0];
    const float* noise = (const float*)d_in[1];
    const float* w1    = (const float*)d_in[2];
    const float* b1    = (const float*)d_in[3];
    const float* w2    = (const float*)d_in[4];
    const float* b2    = (const float*)d_in[5];
    float* out = (float*)d_out;

    cudaFuncSetAttribute(nca_mma_kernel,
                         cudaFuncAttributeMaxDynamicSharedMemorySize, SMEM_BYTES);
    dim3 block(256, 1, 1);
    dim3 grd(IMH, 32, 1);
    nca_mma_kernel<<<grd, block, SMEM_BYTES>>>(grid, noise, w1, b1, w2, b2, out);
}

// round 10
// speedup vs baseline: 1.7861x; 1.0680x over previous
#include <cuda_runtime.h>
#include <cstdint>

// NCA fused step via warp-level tensor-core MMA (mma.sync m16n8k8 tf32).
// CTA = 256 threads = one image row (256 px). Perception staged to SMEM,
// each warp runs GEMM1 [32px,48]x[48,128] and GEMM2 [32px,128]x[128,16].
// The hidden dim is relabeled (k-pos k <-> D1 col tau(k), tau=[0,2,4,6,1,3,5,7])
// so the D1 fragment IS the A2 fragment after {c0,c2,c1,c3} register rename —
// no shuffle relayout. w2's B-frag compensates by reading hid 2q, 2q+1.

#define TC   16
#define HID  128
#define PCH  48
#define IMH  256
#define IMW  256
#define HW   (IMH * IMW)

// SMEM layout in floats (padded strides 52/132 for conflict-free frag loads)
#define PERC_OFF 0              // [256][52]
#define W1_OFF   13312          // [128][52]  w1[hid][perc], tf32-rounded
#define W2_OFF   19968          // [16][132]  w2[out][hid],  tf32-rounded
#define B1_OFF   22080          // [128]
#define B2_OFF   22208          // [16]
#define SMEM_F   22224
#define SMEM_BYTES (SMEM_F * 4)

__device__ __forceinline__ uint32_t to_tf32(float f) {
    uint32_t r;
    asm("cvt.rna.tf32.f32 %0, %1;" : "=r"(r) : "f"(f));
    return r;
}

__device__ __forceinline__ void mma8(float* d, const uint32_t* a,
                                     uint32_t b0, uint32_t b1) {
    asm volatile(
        "mma.sync.aligned.m16n8k8.row.col.f32.tf32.tf32.f32 "
        "{%0,%1,%2,%3}, {%4,%5,%6,%7}, {%8,%9}, {%0,%1,%2,%3};"
        : "+f"(d[0]), "+f"(d[1]), "+f"(d[2]), "+f"(d[3])
        : "r"(a[0]), "r"(a[1]), "r"(a[2]), "r"(a[3]), "r"(b0), "r"(b1));
}

extern __shared__ float sm[];

__global__ __launch_bounds__(256, 2)
void nca_mma_kernel(const float* __restrict__ grid,
                    const float* __restrict__ noise,
                    const float* __restrict__ w1,
                    const float* __restrict__ b1,
                    const float* __restrict__ w2,
                    const float* __restrict__ b2,
                    float* __restrict__ out)
{
    const int tid = threadIdx.x;
    const int y = blockIdx.x;
    const int b = blockIdx.y;

    // ---- stage weights (tf32-rounded; biases exact) ----
    for (int i = tid; i < HID * PCH; i += 256) {
        int h = i / PCH, p = i - h * PCH;
        sm[W1_OFF + h * 52 + p] = __uint_as_float(to_tf32(w1[i]));
    }
    for (int i = tid; i < TC * HID; i += 256) {
        int o = i >> 7, h = i & 127;
        sm[W2_OFF + o * 132 + h] = __uint_as_float(to_tf32(w2[i]));
    }
    if (tid < HID) sm[B1_OFF + tid] = b1[tid];
    if (tid < TC)  sm[B2_OFF + tid] = b2[tid];

    // ---- perception: thread -> pixel (x = tid) ----
    {
        const int x = tid;
        const int pix = y * IMW + x;
        const bool ym = (y > 0), yp = (y < IMH - 1);
        const bool xm = (x > 0), xp = (x < IMW - 1);
        const float* gb = grid + (size_t)b * TC * HW;

        uint32_t pu[PCH];
        #pragma unroll
        for (int c = 0; c < TC; c++) {
            const float* g = gb + c * HW + pix;
            float n00 = (ym && xm) ? __ldg(g - IMW - 1) : 0.f;
            float n01 = (ym)       ? __ldg(g - IMW)     : 0.f;
            float n02 = (ym && xp) ? __ldg(g - IMW + 1) : 0.f;
            float n10 = (xm)       ? __ldg(g - 1)       : 0.f;
            float n11 =              __ldg(g);
            float n12 = (xp)       ? __ldg(g + 1)       : 0.f;
            float n20 = (yp && xm) ? __ldg(g + IMW - 1) : 0.f;
            float n21 = (yp)       ? __ldg(g + IMW)     : 0.f;
            float n22 = (yp && xp) ? __ldg(g + IMW + 1) : 0.f;
            // sobel_x faithful to reference: [[1,0,1],[2,0,-2],[1,0,-1]]/8
            float sx = (n00 + n02 + 2.f*n10 - 2.f*n12 + n20 - n22) * 0.125f;
            // sobel_y: [[1,2,1],[0,0,0],[-1,-2,-1]]/8
            float sy = (n00 + 2.f*n01 + n02 - n20 - 2.f*n21 - n22) * 0.125f;
            pu[3*c]     = to_tf32(n11);
            pu[3*c + 1] = to_tf32(sx);
            pu[3*c + 2] = to_tf32(sy);
        }
        float4* dst = (float4*)&sm[PERC_OFF + tid * 52];
        const float4* src = (const float4*)pu;
        #pragma unroll
        for (int j = 0; j < 12; j++) dst[j] = src[j];
    }
    __syncthreads();

    // ---- per-warp GEMMs on 32-pixel M tile ----
    const int l = tid & 31, wp = tid >> 5;
    const int g = l >> 2, cq = l & 3;
    const int P0 = wp * 32;

    // Cache A1 fragments: perc[32,48] -> 2 mtiles x 6 ktiles x 4 regs
    uint32_t pa[2][6][4];
    #pragma unroll
    for (int mt = 0; mt < 2; mt++)
        #pragma unroll
        for (int kt = 0; kt < 6; kt++) {
            int base = PERC_OFF + (P0 + 16*mt + g) * 52 + 8*kt + cq;
            pa[mt][kt][0] = __float_as_uint(sm[base]);
            pa[mt][kt][1] = __float_as_uint(sm[base + 8*52]);
            pa[mt][kt][2] = __float_as_uint(sm[base + 4]);
            pa[mt][kt][3] = __float_as_uint(sm[base + 8*52 + 4]);
        }

    float acc[2][2][4] = {};

    #pragma unroll
    for (int n0 = 0; n0 < 4; n0++) {         // hid chunk of 32
        const int H0 = 32 * n0;
        float d[2][4][4] = {};
        // GEMM1: d[mt][nt] += perc x w1^T
        #pragma unroll
        for (int nt = 0; nt < 4; nt++) {
            #pragma unroll
            for (int kt = 0; kt < 6; kt++) {
                int ba = W1_OFF + (H0 + 8*nt + g) * 52 + 8*kt + cq;
                uint32_t wb0 = __float_as_uint(sm[ba]);
                uint32_t wb1 = __float_as_uint(sm[ba + 4]);
                mma8(d[0][nt], pa[0][kt], wb0, wb1);
                mma8(d[1][nt], pa[1][kt], wb0, wb1);
            }
        }
        // bias + relu + tf32; D1 frag -> A2 frag by register rename:
        // k-pos q <-> hid 2q, k-pos q+4 <-> hid 2q+1 (tau relabeling), so
        // a = {c0, c2, c1, c3}; w2 B-frag reads hid 2q, 2q+1 (one float2).
        #pragma unroll
        for (int nt = 0; nt < 4; nt++) {
            float bs0 = sm[B1_OFF + H0 + 8*nt + 2*cq];
            float bs1 = sm[B1_OFF + H0 + 8*nt + 2*cq + 1];
            uint32_t w2b[2][2];
            #pragma unroll
            for (int nt2 = 0; nt2 < 2; nt2++) {
                const float2 wv = *(const float2*)&sm[W2_OFF + (8*nt2 + g) * 132
                                                      + H0 + 8*nt + 2*cq];
                w2b[nt2][0] = __float_as_uint(wv.x);   // B[k=q ]  = w2[o][hid 2q]
                w2b[nt2][1] = __float_as_uint(wv.y);   // B[k=q+4] = w2[o][hid 2q+1]
            }
            #pragma unroll
            for (int mt = 0; mt < 2; mt++) {
                uint32_t a[4];
                a[0] = to_tf32(fmaxf(d[mt][nt][0] + bs0, 0.f));  // (g,   k=q)
                a[1] = to_tf32(fmaxf(d[mt][nt][2] + bs0, 0.f));  // (g+8, k=q)
                a[2] = to_tf32(fmaxf(d[mt][nt][1] + bs1, 0.f));  // (g,   k=q+4)
                a[3] = to_tf32(fmaxf(d[mt][nt][3] + bs1, 0.f));  // (g+8, k=q+4)
                mma8(acc[mt][0], a, w2b[0][0], w2b[0][1]);
                mma8(acc[mt][1], a, w2b[1][0], w2b[1][1]);
            }
        }
    }

    // ---- epilogue: +b2, mask, exact-f32 residual, clip, store ----
    const float* nb = noise + (size_t)b * HW + y * IMW;
    #pragma unroll
    for (int mt = 0; mt < 2; mt++) {
        const int r0 = P0 + 16*mt + g;
        const float m0 = (__ldg(nb + r0)     < 0.5f) ? 1.f : 0.f;
        const float m1 = (__ldg(nb + r0 + 8) < 0.5f) ? 1.f : 0.f;
        #pragma unroll
        for (int nt2 = 0; nt2 < 2; nt2++) {
            const int o0 = 8*nt2 + 2*cq;
            const float bv0 = sm[B2_OFF + o0];
            const float bv1 = sm[B2_OFF + o0 + 1];
            const float* gp0 = grid + ((size_t)b * TC + o0) * HW + y * IMW;
            const float* gp1 = gp0 + HW;
            float* op0 = out + ((size_t)b * TC + o0) * HW + y * IMW;
            float* op1 = op0 + HW;
            float v;
            v = fmaf(acc[mt][nt2][0] + bv0, m0, __ldg(gp0 + r0));
            op0[r0]     = fminf(fmaxf(v, -2.f), 2.f);
            v = fmaf(acc[mt][nt2][1] + bv1, m0, __ldg(gp1 + r0));
            op1[r0]     = fminf(fmaxf(v, -2.f), 2.f);
            v = fmaf(acc[mt][nt2][2] + bv0, m1, __ldg(gp0 + r0 + 8));
            op0[r0 + 8] = fminf(fmaxf(v, -2.f), 2.f);
            v = fmaf(acc[mt][nt2][3] + bv1, m1, __ldg(gp1 + r0 + 8));
            op1[r0 + 8] = fminf(fmaxf(v, -2.f), 2.f);
        }
    }
}

extern "C" void kernel_launch(void* const* d_in, const int* in_sizes, int n_in,
                              void* d_out, int out_size)
{
    const float* grid  = (const float*)d_in[0];
    const float* noise = (const float*)d_in[1];
    const float* w1    = (const float*)d_in[2];
    const float* b1    = (const float*)d_in[3];
    const float* w2    = (const float*)d_in[4];
    const float* b2    = (const float*)d_in[5];
    float* out = (float*)d_out;

    cudaFuncSetAttribute(nca_mma_kernel,
                         cudaFuncAttributeMaxDynamicSharedMemorySize, SMEM_BYTES);
    dim3 block(256, 1, 1);
    dim3 grd(IMH, 32, 1);
    nca_mma_kernel<<<grd, block, SMEM_BYTES>>>(grid, noise, w1, b1, w2, b2, out);
}

// round 11
// speedup vs baseline: 1.9608x; 1.0978x over previous
#include <cuda_runtime.h>
#include <cstdint>

// NCA fused step via warp-level tensor-core MMA (mma.sync m16n8k8 tf32).
// CTA = 256 threads = 128 pixels (half an image row). Perception is computed
// by 2 threads/pixel (channel split) into SMEM; each warp then runs
// GEMM1 [16px,48]x[48,128] and GEMM2 [16px,128]x[128,16] on one 16-px M tile.
// Hidden dim relabeled (k-pos q <-> hid 2q / q+4 <-> 2q+1) so D1 frag == A2
// frag after {c0,c2,c1,c3} register rename — no shuffles between GEMMs.
// 1 M-tile/warp keeps regs <= 85 so 3 CTAs (24 warps) fit per SM.

#define TC   16
#define HID  128
#define PCH  48
#define IMH  256
#define IMW  256
#define HW   (IMH * IMW)

// SMEM layout in floats (padded strides 52/132 for conflict-free frag loads)
#define PERC_OFF 0              // [128][52]
#define W1_OFF   6656           // [128][52]  w1[hid][perc], tf32-rounded
#define W2_OFF   13312          // [16][132]  w2[out][hid],  tf32-rounded
#define B1_OFF   15424          // [128]
#define B2_OFF   15552          // [16]
#define SMEM_F   15568
#define SMEM_BYTES (SMEM_F * 4)

__device__ __forceinline__ uint32_t to_tf32(float f) {
    uint32_t r;
    asm("cvt.rna.tf32.f32 %0, %1;" : "=r"(r) : "f"(f));
    return r;
}

__device__ __forceinline__ void mma8(float* d, const uint32_t* a,
                                     uint32_t b0, uint32_t b1) {
    asm volatile(
        "mma.sync.aligned.m16n8k8.row.col.f32.tf32.tf32.f32 "
        "{%0,%1,%2,%3}, {%4,%5,%6,%7}, {%8,%9}, {%0,%1,%2,%3};"
        : "+f"(d[0]), "+f"(d[1]), "+f"(d[2]), "+f"(d[3])
        : "r"(a[0]), "r"(a[1]), "r"(a[2]), "r"(a[3]), "r"(b0), "r"(b1));
}

extern __shared__ float sm[];

__global__ __launch_bounds__(256, 3)
void nca_mma_kernel(const float* __restrict__ grid,
                    const float* __restrict__ noise,
                    const float* __restrict__ w1,
                    const float* __restrict__ b1,
                    const float* __restrict__ w2,
                    const float* __restrict__ b2,
                    float* __restrict__ out)
{
    const int tid = threadIdx.x;
    const int x0 = blockIdx.x * 128;
    const int y = blockIdx.y;
    const int b = blockIdx.z;

    // ---- stage weights (tf32-rounded; biases exact) ----
    for (int i = tid; i < HID * PCH; i += 256) {
        int h = i / PCH, p = i - h * PCH;
        sm[W1_OFF + h * 52 + p] = __uint_as_float(to_tf32(w1[i]));
    }
    for (int i = tid; i < TC * HID; i += 256) {
        int o = i >> 7, h = i & 127;
        sm[W2_OFF + o * 132 + h] = __uint_as_float(to_tf32(w2[i]));
    }
    if (tid < HID) sm[B1_OFF + tid] = b1[tid];
    if (tid < TC)  sm[B2_OFF + tid] = b2[tid];

    // ---- perception: 2 threads per pixel (channel split 8+8) ----
    {
        const int px = tid & 127;           // pixel within tile
        const int cb = (tid >> 7) << 3;     // channel base: 0 or 8
        const int x = x0 + px;
        const int pix = y * IMW + x;
        const bool ym = (y > 0), yp = (y < IMH - 1);
        const bool xm = (x > 0), xp = (x < IMW - 1);
        const float* gb = grid + ((size_t)b * TC + cb) * HW;

        uint32_t pu[24];
        #pragma unroll
        for (int cc = 0; cc < 8; cc++) {
            const float* g = gb + cc * HW + pix;
            float n00 = (ym && xm) ? __ldg(g - IMW - 1) : 0.f;
            float n01 = (ym)       ? __ldg(g - IMW)     : 0.f;
            float n02 = (ym && xp) ? __ldg(g - IMW + 1) : 0.f;
            float n10 = (xm)       ? __ldg(g - 1)       : 0.f;
            float n11 =              __ldg(g);
            float n12 = (xp)       ? __ldg(g + 1)       : 0.f;
            float n20 = (yp && xm) ? __ldg(g + IMW - 1) : 0.f;
            float n21 = (yp)       ? __ldg(g + IMW)     : 0.f;
            float n22 = (yp && xp) ? __ldg(g + IMW + 1) : 0.f;
            // sobel_x faithful to reference: [[1,0,1],[2,0,-2],[1,0,-1]]/8
            float sx = (n00 + n02 + 2.f*n10 - 2.f*n12 + n20 - n22) * 0.125f;
            // sobel_y: [[1,2,1],[0,0,0],[-1,-2,-1]]/8
            float sy = (n00 + 2.f*n01 + n02 - n20 - 2.f*n21 - n22) * 0.125f;
            pu[3*cc]     = to_tf32(n11);
            pu[3*cc + 1] = to_tf32(sx);
            pu[3*cc + 2] = to_tf32(sy);
        }
        float4* dst = (float4*)&sm[PERC_OFF + px * 52 + 3 * cb];
        const float4* src = (const float4*)pu;
        #pragma unroll
        for (int j = 0; j < 6; j++) dst[j] = src[j];
    }
    __syncthreads();

    // ---- per-warp GEMMs on one 16-pixel M tile ----
    const int l = tid & 31, wp = tid >> 5;
    const int g = l >> 2, cq = l & 3;
    const int P0 = wp * 16;

    // Cache A1 fragments: perc[16,48] -> 6 ktiles x 4 regs
    uint32_t pa[6][4];
    #pragma unroll
    for (int kt = 0; kt < 6; kt++) {
        int base = PERC_OFF + (P0 + g) * 52 + 8*kt + cq;
        pa[kt][0] = __float_as_uint(sm[base]);
        pa[kt][1] = __float_as_uint(sm[base + 8*52]);
        pa[kt][2] = __float_as_uint(sm[base + 4]);
        pa[kt][3] = __float_as_uint(sm[base + 8*52 + 4]);
    }

    float acc[2][4] = {};

    #pragma unroll
    for (int n0 = 0; n0 < 4; n0++) {         // hid chunk of 32
        const int H0 = 32 * n0;
        float d[4][4] = {};
        // GEMM1: d[nt] += perc x w1^T
        #pragma unroll
        for (int nt = 0; nt < 4; nt++) {
            #pragma unroll
            for (int kt = 0; kt < 6; kt++) {
                int ba = W1_OFF + (H0 + 8*nt + g) * 52 + 8*kt + cq;
                uint32_t wb0 = __float_as_uint(sm[ba]);
                uint32_t wb1 = __float_as_uint(sm[ba + 4]);
                mma8(d[nt], pa[kt], wb0, wb1);
            }
        }
        // bias + relu + tf32; D1 frag -> A2 frag by register rename:
        // k-pos q <-> hid 2q, k-pos q+4 <-> hid 2q+1, so a = {c0,c2,c1,c3};
        // w2 B-frag compensates by reading hid 2q, 2q+1 (one float2).
        #pragma unroll
        for (int nt = 0; nt < 4; nt++) {
            float bs0 = sm[B1_OFF + H0 + 8*nt + 2*cq];
            float bs1 = sm[B1_OFF + H0 + 8*nt + 2*cq + 1];
            uint32_t a[4];
            a[0] = to_tf32(fmaxf(d[nt][0] + bs0, 0.f));  // (g,   k=q)
            a[1] = to_tf32(fmaxf(d[nt][2] + bs0, 0.f));  // (g+8, k=q)
            a[2] = to_tf32(fmaxf(d[nt][1] + bs1, 0.f));  // (g,   k=q+4)
            a[3] = to_tf32(fmaxf(d[nt][3] + bs1, 0.f));  // (g+8, k=q+4)
            #pragma unroll
            for (int nt2 = 0; nt2 < 2; nt2++) {
                const float2 wv = *(const float2*)&sm[W2_OFF + (8*nt2 + g) * 132
                                                      + H0 + 8*nt + 2*cq];
                mma8(acc[nt2], a, __float_as_uint(wv.x), __float_as_uint(wv.y));
            }
        }
    }

    // ---- epilogue: +b2, mask, exact-f32 residual, clip, store ----
    const float* nb = noise + (size_t)b * HW + y * IMW + x0;
    const int r0 = P0 + g;
    const float m0 = (__ldg(nb + r0)     < 0.5f) ? 1.f : 0.f;
    const float m1 = (__ldg(nb + r0 + 8) < 0.5f) ? 1.f : 0.f;
    #pragma unroll
    for (int nt2 = 0; nt2 < 2; nt2++) {
        const int o0 = 8*nt2 + 2*cq;
        const float bv0 = sm[B2_OFF + o0];
        const float bv1 = sm[B2_OFF + o0 + 1];
        const float* gp0 = grid + ((size_t)b * TC + o0) * HW + y * IMW + x0;
        const float* gp1 = gp0 + HW;
        float* op0 = out + ((size_t)b * TC + o0) * HW + y * IMW + x0;
        float* op1 = op0 + HW;
        float v;
        v = fmaf(acc[nt2][0] + bv0, m0, __ldg(gp0 + r0));
        op0[r0]     = fminf(fmaxf(v, -2.f), 2.f);
        v = fmaf(acc[nt2][1] + bv1, m0, __ldg(gp1 + r0));
        op1[r0]     = fminf(fmaxf(v, -2.f), 2.f);
        v = fmaf(acc[nt2][2] + bv0, m1, __ldg(gp0 + r0 + 8));
        op0[r0 + 8] = fminf(fmaxf(v, -2.f), 2.f);
        v = fmaf(acc[nt2][3] + bv1, m1, __ldg(gp1 + r0 + 8));
        op1[r0 + 8] = fminf(fmaxf(v, -2.f), 2.f);
    }
}

extern "C" void kernel_launch(void* const* d_in, const int* in_sizes, int n_in,
                              void* d_out, int out_size)
{
    const float* grid  = (const float*)d_in[0];
    const float* noise = (const float*)d_in[1];
    const float* w1    = (const float*)d_in[2];
    const float* b1    = (const float*)d_in[3];
    const float* w2    = (const float*)d_in[4];
    const float* b2    = (const float*)d_in[5];
    float* out = (float*)d_out;

    cudaFuncSetAttribute(nca_mma_kernel,
                         cudaFuncAttributeMaxDynamicSharedMemorySize, SMEM_BYTES);
    dim3 block(256, 1, 1);
    dim3 grd(IMW / 128, IMH, 32);
    nca_mma_kernel<<<grd, block, SMEM_BYTES>>>(grid, noise, w1, b1, w2, b2, out);
}

// round 12
// speedup vs baseline: 1.9613x; 1.0003x over previous
#include <cuda_runtime.h>
#include <cstdint>

// NCA fused step via warp-level tensor-core MMA (mma.sync m16n8k8 tf32).
// CTA = 256 threads = 128 pixels. Perception by 2 threads/pixel (channel
// split) into SMEM; each warp runs GEMM1 [16px,48]x[48,128] and GEMM2
// [16px,128]x[128,16] on one 16-px M tile.
// ILP layout: GEMM1 kt-outer/nt-inner (4 independent d-chains, distance 4);
// GEMM2 accumulators split by n0 parity (4 independent chains, merged at end).
// Hidden dim relabeled (k-pos q <-> hid 2q, q+4 <-> 2q+1) so D1 frag == A2
// frag after {c0,c2,c1,c3} register rename — no shuffles between GEMMs.

#define TC   16
#define HID  128
#define PCH  48
#define IMH  256
#define IMW  256
#define HW   (IMH * IMW)

// SMEM layout in floats (padded strides 52/132 for conflict-free frag loads)
#define PERC_OFF 0              // [128][52]
#define W1_OFF   6656           // [128][52]  w1[hid][perc], tf32-rounded
#define W2_OFF   13312          // [16][132]  w2[out][hid],  tf32-rounded
#define B1_OFF   15424          // [128]
#define B2_OFF   15552          // [16]
#define SMEM_F   15568
#define SMEM_BYTES (SMEM_F * 4)

__device__ __forceinline__ uint32_t to_tf32(float f) {
    uint32_t r;
    asm("cvt.rna.tf32.f32 %0, %1;" : "=r"(r) : "f"(f));
    return r;
}

__device__ __forceinline__ void mma8(float* d, const uint32_t* a,
                                     uint32_t b0, uint32_t b1) {
    asm volatile(
        "mma.sync.aligned.m16n8k8.row.col.f32.tf32.tf32.f32 "
        "{%0,%1,%2,%3}, {%4,%5,%6,%7}, {%8,%9}, {%0,%1,%2,%3};"
        : "+f"(d[0]), "+f"(d[1]), "+f"(d[2]), "+f"(d[3])
        : "r"(a[0]), "r"(a[1]), "r"(a[2]), "r"(a[3]), "r"(b0), "r"(b1));
}

extern __shared__ float sm[];

__global__ __launch_bounds__(256, 3)
void nca_mma_kernel(const float* __restrict__ grid,
                    const float* __restrict__ noise,
                    const float* __restrict__ w1,
                    const float* __restrict__ b1,
                    const float* __restrict__ w2,
                    const float* __restrict__ b2,
                    float* __restrict__ out)
{
    const int tid = threadIdx.x;
    const int x0 = blockIdx.x * 128;
    const int y = blockIdx.y;
    const int b = blockIdx.z;

    // ---- stage weights (tf32-rounded; biases exact) ----
    for (int i = tid; i < HID * PCH; i += 256) {
        int h = i / PCH, p = i - h * PCH;
        sm[W1_OFF + h * 52 + p] = __uint_as_float(to_tf32(w1[i]));
    }
    for (int i = tid; i < TC * HID; i += 256) {
        int o = i >> 7, h = i & 127;
        sm[W2_OFF + o * 132 + h] = __uint_as_float(to_tf32(w2[i]));
    }
    if (tid < HID) sm[B1_OFF + tid] = b1[tid];
    if (tid < TC)  sm[B2_OFF + tid] = b2[tid];

    // ---- perception: 2 threads per pixel (channel split 8+8) ----
    {
        const int px = tid & 127;           // pixel within tile
        const int cb = (tid >> 7) << 3;     // channel base: 0 or 8
        const int x = x0 + px;
        const int pix = y * IMW + x;
        const bool ym = (y > 0), yp = (y < IMH - 1);
        const bool xm = (x > 0), xp = (x < IMW - 1);
        const float* gb = grid + ((size_t)b * TC + cb) * HW;

        uint32_t pu[24];
        #pragma unroll
        for (int cc = 0; cc < 8; cc++) {
            const float* g = gb + cc * HW + pix;
            float n00 = (ym && xm) ? __ldg(g - IMW - 1) : 0.f;
            float n01 = (ym)       ? __ldg(g - IMW)     : 0.f;
            float n02 = (ym && xp) ? __ldg(g - IMW + 1) : 0.f;
            float n10 = (xm)       ? __ldg(g - 1)       : 0.f;
            float n11 =              __ldg(g);
            float n12 = (xp)       ? __ldg(g + 1)       : 0.f;
            float n20 = (yp && xm) ? __ldg(g + IMW - 1) : 0.f;
            float n21 = (yp)       ? __ldg(g + IMW)     : 0.f;
            float n22 = (yp && xp) ? __ldg(g + IMW + 1) : 0.f;
            // sobel_x faithful to reference: [[1,0,1],[2,0,-2],[1,0,-1]]/8
            float sx = (n00 + n02 + 2.f*n10 - 2.f*n12 + n20 - n22) * 0.125f;
            // sobel_y: [[1,2,1],[0,0,0],[-1,-2,-1]]/8
            float sy = (n00 + 2.f*n01 + n02 - n20 - 2.f*n21 - n22) * 0.125f;
            pu[3*cc]     = to_tf32(n11);
            pu[3*cc + 1] = to_tf32(sx);
            pu[3*cc + 2] = to_tf32(sy);
        }
        float4* dst = (float4*)&sm[PERC_OFF + px * 52 + 3 * cb];
        const float4* src = (const float4*)pu;
        #pragma unroll
        for (int j = 0; j < 6; j++) dst[j] = src[j];
    }
    __syncthreads();

    // ---- per-warp GEMMs on one 16-pixel M tile ----
    const int l = tid & 31, wp = tid >> 5;
    const int g = l >> 2, cq = l & 3;
    const int P0 = wp * 16;

    // hoisted SMEM bases (all loop offsets become compile-time constants)
    const int pa_base = PERC_OFF + (P0 + g) * 52 + cq;
    const int w1_base = W1_OFF + g * 52 + cq;
    const int w2_base = W2_OFF + g * 132 + 2 * cq;
    const int b1_base = B1_OFF + 2 * cq;

    float acc[2][2][4] = {};   // [n0 parity][nt2][frag]

    #pragma unroll
    for (int n0 = 0; n0 < 4; n0++) {         // hid chunk of 32
        const int H0 = 32 * n0;
        float d[4][4] = {};
        // GEMM1: kt outer, nt inner -> 4 independent accumulation chains
        #pragma unroll
        for (int kt = 0; kt < 6; kt++) {
            uint32_t a[4];
            a[0] = __float_as_uint(sm[pa_base + 8*kt]);
            a[1] = __float_as_uint(sm[pa_base + 8*kt + 8*52]);
            a[2] = __float_as_uint(sm[pa_base + 8*kt + 4]);
            a[3] = __float_as_uint(sm[pa_base + 8*kt + 8*52 + 4]);
            #pragma unroll
            for (int nt = 0; nt < 4; nt++) {
                const int ba = w1_base + (H0 + 8*nt) * 52 + 8*kt;
                mma8(d[nt], a, __float_as_uint(sm[ba]),
                               __float_as_uint(sm[ba + 4]));
            }
        }
        // bias + relu + tf32; D1 frag -> A2 frag by register rename:
        // k-pos q <-> hid 2q, k-pos q+4 <-> hid 2q+1, so a = {c0,c2,c1,c3};
        // w2 B-frag compensates by reading hid 2q, 2q+1 (one float2).
        float* ac0 = acc[n0 & 1][0];
        float* ac1 = acc[n0 & 1][1];
        #pragma unroll
        for (int nt = 0; nt < 4; nt++) {
            const float bs0 = sm[b1_base + H0 + 8*nt];
            const float bs1 = sm[b1_base + H0 + 8*nt + 1];
            uint32_t a[4];
            a[0] = to_tf32(fmaxf(d[nt][0] + bs0, 0.f));  // (g,   k=q)
            a[1] = to_tf32(fmaxf(d[nt][2] + bs0, 0.f));  // (g+8, k=q)
            a[2] = to_tf32(fmaxf(d[nt][1] + bs1, 0.f));  // (g,   k=q+4)
            a[3] = to_tf32(fmaxf(d[nt][3] + bs1, 0.f));  // (g+8, k=q+4)
            const float2 wv0 = *(const float2*)&sm[w2_base + H0 + 8*nt];
            const float2 wv1 = *(const float2*)&sm[w2_base + 8*132 + H0 + 8*nt];
            mma8(ac0, a, __float_as_uint(wv0.x), __float_as_uint(wv0.y));
            mma8(ac1, a, __float_as_uint(wv1.x), __float_as_uint(wv1.y));
        }
    }

    // merge parity-split accumulators
    float accf[2][4];
    #pragma unroll
    for (int nt2 = 0; nt2 < 2; nt2++)
        #pragma unroll
        for (int i = 0; i < 4; i++)
            accf[nt2][i] = acc[0][nt2][i] + acc[1][nt2][i];

    // ---- epilogue: +b2, mask, exact-f32 residual, clip, store ----
    const float* nb = noise + (size_t)b * HW + y * IMW + x0;
    const int r0 = P0 + g;
    const float m0 = (__ldg(nb + r0)     < 0.5f) ? 1.f : 0.f;
    const float m1 = (__ldg(nb + r0 + 8) < 0.5f) ? 1.f : 0.f;
    #pragma unroll
    for (int nt2 = 0; nt2 < 2; nt2++) {
        const int o0 = 8*nt2 + 2*cq;
        const float bv0 = sm[B2_OFF + o0];
        const float bv1 = sm[B2_OFF + o0 + 1];
        const float* gp0 = grid + ((size_t)b * TC + o0) * HW + y * IMW + x0;
        const float* gp1 = gp0 + HW;
        float* op0 = out + ((size_t)b * TC + o0) * HW + y * IMW + x0;
        float* op1 = op0 + HW;
        float v;
        v = fmaf(accf[nt2][0] + bv0, m0, __ldg(gp0 + r0));
        op0[r0]     = fminf(fmaxf(v, -2.f), 2.f);
        v = fmaf(accf[nt2][1] + bv1, m0, __ldg(gp1 + r0));
        op1[r0]     = fminf(fmaxf(v, -2.f), 2.f);
        v = fmaf(accf[nt2][2] + bv0, m1, __ldg(gp0 + r0 + 8));
        op0[r0 + 8] = fminf(fmaxf(v, -2.f), 2.f);
        v = fmaf(accf[nt2][3] + bv1, m1, __ldg(gp1 + r0 + 8));
        op1[r0 + 8] = fminf(fmaxf(v, -2.f), 2.f);
    }
}

extern "C" void kernel_launch(void* const* d_in, const int* in_sizes, int n_in,
                              void* d_out, int out_size)
{
    const float* grid  = (const float*)d_in[0];
    const float* noise = (const float*)d_in[1];
    const float* w1    = (const float*)d_in[2];
    const float* b1    = (const float*)d_in[3];
    const float* w2    = (const float*)d_in[4];
    const float* b2    = (const float*)d_in[5];
    float* out = (float*)d_out;

    cudaFuncSetAttribute(nca_mma_kernel,
                         cudaFuncAttributeMaxDynamicSharedMemorySize, SMEM_BYTES);
    dim3 block(256, 1, 1);
    dim3 grd(IMW / 128, IMH, 32);
    nca_mma_kernel<<<grd, block, SMEM_BYTES>>>(grid, noise, w1, b1, w2, b2, out);
}

// round 14
// speedup vs baseline: 2.8823x; 1.4696x over previous
#include <cuda_runtime.h>
#include <cuda_bf16.h>
#include <cstdint>

// NCA fused step via bf16 tensor-core MMA (mma.sync m16n8k16 bf16->f32).
// CTA = 256 threads = 128 pixels. Perception by 2 threads/pixel (channel
// split), f32 stencil -> bf16x2 packed into SMEM. Each warp runs
// GEMM1 [16px,48]x[48,128] and GEMM2 [16px,128]x[128,16] on one 16-px tile.
// bf16 A-frag k-pairs are adjacent, so D1 frag -> A2 frag is a pure
// cvt-pack (no shuffles, no relabeling). Residual/mask/clip exact f32.
// 32.8 KB SMEM + <=64 regs -> 4 CTAs/SM (32 warps, 50% occ).

#define TC   16
#define HID  128
#define PCH  48
#define IMH  256
#define IMW  256
#define HW   (IMH * IMW)

// byte offsets in SMEM arena
#define PERC_B 0        // [128 px][56 bf16]  (112 B rows; 48 used)
#define W1_B   14336    // [128 hid][56 bf16] (112 B rows)
#define W2_B   28672    // [16 out][136 bf16] (272 B rows; 128 used)
#define B1_B   33024    // [128] f32
#define B2_B   33536    // [16] f32
#define SMEM_BYTES 33600

__device__ __forceinline__ void mma16(float* d, const uint32_t* a,
                                      uint32_t b0, uint32_t b1) {
    asm volatile(
        "mma.sync.aligned.m16n8k16.row.col.f32.bf16.bf16.f32 "
        "{%0,%1,%2,%3}, {%4,%5,%6,%7}, {%8,%9}, {%0,%1,%2,%3};"
        : "+f"(d[0]), "+f"(d[1]), "+f"(d[2]), "+f"(d[3])
        : "r"(a[0]), "r"(a[1]), "r"(a[2]), "r"(a[3]), "r"(b0), "r"(b1));
}

__device__ __forceinline__ uint32_t packbf(float lo, float hi) {
    __nv_bfloat162 v = __floats2bfloat162_rn(lo, hi);   // .x = lo half
    return *(uint32_t*)&v;
}

extern __shared__ char smc[];

__global__ __launch_bounds__(256, 4)
void nca_mma_kernel(const float* __restrict__ grid,
                    const float* __restrict__ noise,
                    const float* __restrict__ w1,
                    const float* __restrict__ b1,
                    const float* __restrict__ w2,
                    const float* __restrict__ b2,
                    float* __restrict__ out)
{
    const int tid = threadIdx.x;
    const int x0 = blockIdx.x * 128;
    const int y = blockIdx.y;
    const int b = blockIdx.z;

    // ---- stage weights as bf16 (biases exact f32) ----
    {
        __nv_bfloat16* w1s = (__nv_bfloat16*)(smc + W1_B);
        for (int i = tid; i < HID * PCH; i += 256) {
            int h = i / PCH, p = i - h * PCH;
            w1s[h * 56 + p] = __float2bfloat16(w1[i]);
        }
        __nv_bfloat16* w2s = (__nv_bfloat16*)(smc + W2_B);
        for (int i = tid; i < TC * HID; i += 256) {
            int o = i >> 7, h = i & 127;
            w2s[o * 136 + h] = __float2bfloat16(w2[i]);
        }
        if (tid < HID) ((float*)(smc + B1_B))[tid] = b1[tid];
        if (tid < TC)  ((float*)(smc + B2_B))[tid] = b2[tid];
    }

    // ---- perception: 2 threads per pixel (channel split 8+8) ----
    {
        const int px = tid & 127;           // pixel within tile
        const int cb = (tid >> 7) << 3;     // channel base: 0 or 8
        const int x = x0 + px;
        const int pix = y * IMW + x;
        const bool ym = (y > 0), yp = (y < IMH - 1);
        const bool xm = (x > 0), xp = (x < IMW - 1);
        const float* gb = grid + ((size_t)b * TC + cb) * HW;

        float v[24];
        #pragma unroll
        for (int cc = 0; cc < 8; cc++) {
            const float* g = gb + cc * HW + pix;
            float n00 = (ym && xm) ? __ldg(g - IMW - 1) : 0.f;
            float n01 = (ym)       ? __ldg(g - IMW)     : 0.f;
            float n02 = (ym && xp) ? __ldg(g - IMW + 1) : 0.f;
            float n10 = (xm)       ? __ldg(g - 1)       : 0.f;
            float n11 =              __ldg(g);
            float n12 = (xp)       ? __ldg(g + 1)       : 0.f;
            float n20 = (yp && xm) ? __ldg(g + IMW - 1) : 0.f;
            float n21 = (yp)       ? __ldg(g + IMW)     : 0.f;
            float n22 = (yp && xp) ? __ldg(g + IMW + 1) : 0.f;
            // sobel_x faithful to reference: [[1,0,1],[2,0,-2],[1,0,-1]]/8
            float sx = (n00 + n02 + 2.f*n10 - 2.f*n12 + n20 - n22) * 0.125f;
            // sobel_y: [[1,2,1],[0,0,0],[-1,-2,-1]]/8
            float sy = (n00 + 2.f*n01 + n02 - n20 - 2.f*n21 - n22) * 0.125f;
            v[3*cc]     = n11;
            v[3*cc + 1] = sx;
            v[3*cc + 2] = sy;
        }
        uint32_t pw[12];
        #pragma unroll
        for (int m = 0; m < 12; m++) pw[m] = packbf(v[2*m], v[2*m + 1]);
        uint4* dst = (uint4*)(smc + PERC_B + px * 112 + cb * 6);
        const uint4* src = (const uint4*)pw;
        dst[0] = src[0]; dst[1] = src[1]; dst[2] = src[2];
    }
    __syncthreads();

    // ---- per-warp GEMMs on one 16-pixel M tile ----
    const int l = tid & 31, wp = tid >> 5;
    const int g = l >> 2, cq = l & 3;
    const int P0 = wp * 16;

    // A1 fragments (perception), loaded once, reused across all hid chunks.
    // chunk kc covers k = 16kc..16kc+15; conflict-free (28g+cq distinct mod 32).
    uint32_t a1[3][4];
    {
        const char* pb = smc + PERC_B + (P0 + g) * 112 + cq * 4;
        #pragma unroll
        for (int kc = 0; kc < 3; kc++) {
            a1[kc][0] = *(const uint32_t*)(pb + kc * 32);             // (g,   k=2cq)
            a1[kc][1] = *(const uint32_t*)(pb + kc * 32 + 8 * 112);   // (g+8, k=2cq)
            a1[kc][2] = *(const uint32_t*)(pb + kc * 32 + 16);        // (g,   k=2cq+8)
            a1[kc][3] = *(const uint32_t*)(pb + kc * 32 + 16 + 8 * 112);
        }
    }

    const char* w1c = smc + W1_B + g * 112 + cq * 4;
    const char* w2c = smc + W2_B + g * 272 + cq * 4;
    const float* b1s = (const float*)(smc + B1_B);

    float acc[2][4] = {};

    #pragma unroll
    for (int n0 = 0; n0 < 4; n0++) {         // hid chunk of 32
        const int H0 = 32 * n0;
        float d[4][4] = {};
        // GEMM1: kc outer, nt inner (4 independent d-chains)
        #pragma unroll
        for (int kc = 0; kc < 3; kc++) {
            #pragma unroll
            for (int nt = 0; nt < 4; nt++) {
                const char* ba = w1c + (H0 + 8*nt) * 112 + kc * 32;
                mma16(d[nt], a1[kc], *(const uint32_t*)ba,
                                     *(const uint32_t*)(ba + 16));
            }
        }
        // bias + relu + bf16 pack: D1 frag -> A2 frag directly.
        // GEMM2 k-chunk (16 hid) = two nt tiles; a2[0..1] from ntA, a2[2..3] from ntB.
        #pragma unroll
        for (int half = 0; half < 2; half++) {
            const int ntA = 2 * half, ntB = ntA + 1;
            const float bA0 = b1s[H0 + 8*ntA + 2*cq];
            const float bA1 = b1s[H0 + 8*ntA + 2*cq + 1];
            const float bB0 = b1s[H0 + 8*ntB + 2*cq];
            const float bB1 = b1s[H0 + 8*ntB + 2*cq + 1];
            uint32_t a2[4];
            a2[0] = packbf(fmaxf(d[ntA][0] + bA0, 0.f),
                           fmaxf(d[ntA][1] + bA1, 0.f));   // (g,   k=2cq,2cq+1)
            a2[1] = packbf(fmaxf(d[ntA][2] + bA0, 0.f),
                           fmaxf(d[ntA][3] + bA1, 0.f));   // (g+8, k=2cq,2cq+1)
            a2[2] = packbf(fmaxf(d[ntB][0] + bB0, 0.f),
                           fmaxf(d[ntB][1] + bB1, 0.f));   // (g,   k=2cq+8,+9)
            a2[3] = packbf(fmaxf(d[ntB][2] + bB0, 0.f),
                           fmaxf(d[ntB][3] + bB1, 0.f));   // (g+8, k=2cq+8,+9)
            const int kb2 = (H0 + 16 * half) * 2;          // bytes into w2 row
            #pragma unroll
            for (int nt2 = 0; nt2 < 2; nt2++) {
                const char* bb = w2c + nt2 * (8 * 272) + kb2;
                mma16(acc[nt2], a2, *(const uint32_t*)bb,
                                    *(const uint32_t*)(bb + 16));
            }
        }
    }

    // ---- epilogue: +b2, mask, exact-f32 residual, clip, store ----
    const float* b2s = (const float*)(smc + B2_B);
    const float* nb = noise + (size_t)b * HW + y * IMW + x0;
    const int r0 = P0 + g;
    const float m0 = (__ldg(nb + r0)     < 0.5f) ? 1.f : 0.f;
    const float m1 = (__ldg(nb + r0 + 8) < 0.5f) ? 1.f : 0.f;
    #pragma unroll
    for (int nt2 = 0; nt2 < 2; nt2++) {
        const int o0 = 8*nt2 + 2*cq;
        const float bv0 = b2s[o0];
        const float bv1 = b2s[o0 + 1];
        const float* gp0 = grid + ((size_t)b * TC + o0) * HW + y * IMW + x0;
        const float* gp1 = gp0 + HW;
        float* op0 = out + ((size_t)b * TC + o0) * HW + y * IMW + x0;
        float* op1 = op0 + HW;
        float v;
        v = fmaf(acc[nt2][0] + bv0, m0, __ldg(gp0 + r0));
        op0[r0]     = fminf(fmaxf(v, -2.f), 2.f);
        v = fmaf(acc[nt2][1] + bv1, m0, __ldg(gp1 + r0));
        op1[r0]     = fminf(fmaxf(v, -2.f), 2.f);
        v = fmaf(acc[nt2][2] + bv0, m1, __ldg(gp0 + r0 + 8));
        op0[r0 + 8] = fminf(fmaxf(v, -2.f), 2.f);
        v = fmaf(acc[nt2][3] + bv1, m1, __ldg(gp1 + r0 + 8));
        op1[r0 + 8] = fminf(fmaxf(v, -2.f), 2.f);
    }
}

extern "C" void kernel_launch(void* const* d_in, const int* in_sizes, int n_in,
                              void* d_out, int out_size)
{
    const float* grid  = (const float*)d_in[0];
    const float* noise = (const float*)d_in[1];
    const float* w1    = (const float*)d_in[2];
    const float* b1    = (const float*)d_in[3];
    const float* w2    = (const float*)d_in[4];
    const float* b2    = (const float*)d_in[5];
    float* out = (float*)d_out;

    cudaFuncSetAttribute(nca_mma_kernel,
                         cudaFuncAttributeMaxDynamicSharedMemorySize, SMEM_BYTES);
    dim3 block(256, 1, 1);
    dim3 grd(IMW / 128, IMH, 32);
    nca_mma_kernel<<<grd, block, SMEM_BYTES>>>(grid, noise, w1, b1, w2, b2, out);
}

// round 16
// speedup vs baseline: 3.4407x; 1.1937x over previous
#include <cuda_runtime.h>
#include <cuda_bf16.h>
#include <cstdint>

// NCA fused step via bf16 tensor-core MMA (mma.sync m16n8k16 bf16->f32).
// CTA = 256 threads = 128 pixels. Perception 2 threads/pixel into SMEM.
// k-pair interleave (per 16-k chunk: p0,p4,p1,p5,p2,p6,p3,p7) makes every
// fragment's (k=2q, k=2q+8) register pair 8 adjacent bytes -> LDS.64.
// Rows padded to 160/288 B so LDS.64 is bank-conflict-free (40-word stride).
// Weights pre-converted to the exact SMEM image by a prep kernel into
// __device__ scratch; main kernel stages them with cp.async (no cvt/div).

#define TC   16
#define HID  128
#define PCH  48
#define IMH  256
#define IMW  256
#define HW   (IMH * IMW)

// SMEM byte offsets
#define PERC_B 0        // [128 px][160 B]  (96 B used: 24 bf16-pairs, pi-order)
#define W1_B   20480    // [128 hid][160 B] (96 B used)
#define W2_B   40960    // [16 out][288 B]  (256 B used)
#define B1_B   45568    // [128] f32
#define B2_B   46080    // [16] f32
#define SMEM_BYTES 46144

#define WIMG_U32 6272   // 128*40 + 16*72
__device__ uint32_t g_wimg[WIMG_U32];

__device__ __forceinline__ uint32_t packbf(float lo, float hi) {
    __nv_bfloat162 v = __floats2bfloat162_rn(lo, hi);   // .x = lo half
    return *(uint32_t*)&v;
}

__device__ __forceinline__ void mma16(float* d, const uint32_t* a,
                                      uint32_t b0, uint32_t b1) {
    asm volatile(
        "mma.sync.aligned.m16n8k16.row.col.f32.bf16.bf16.f32 "
        "{%0,%1,%2,%3}, {%4,%5,%6,%7}, {%8,%9}, {%0,%1,%2,%3};"
        : "+f"(d[0]), "+f"(d[1]), "+f"(d[2]), "+f"(d[3])
        : "r"(a[0]), "r"(a[1]), "r"(a[2]), "r"(a[3]), "r"(b0), "r"(b1));
}

__device__ __forceinline__ uint32_t smem_u32(const void* p) {
    uint32_t a;
    asm("{ .reg .u64 t; cvta.to.shared.u64 t, %1; cvt.u32.u64 %0, t; }" : "=r"(a) : "l"(p));
    return a;
}

__device__ __forceinline__ void cp16(uint32_t saddr, const void* g) {
    asm volatile("cp.async.ca.shared.global [%0], [%1], 16;"
                 :: "r"(saddr), "l"(g) : "memory");
}

// ---- prep: build the bf16 pi-permuted SMEM image of w1/w2 in GMEM ----
__global__ void prep_kernel(const float* __restrict__ w1,
                            const float* __restrict__ w2)
{
    const int t = blockIdx.x * 256 + threadIdx.x;
    // w1: 128 rows x 24 pairs (stride 40 u32)
    for (int i = t; i < 128 * 24; i += gridDim.x * 256) {
        int h = i / 24, pr = i - h * 24;
        int kc = pr >> 3, p = pr & 7;
        int pos = (p < 4) ? 2 * p : 2 * (p - 4) + 1;
        int k = 16 * kc + 2 * p;
        g_wimg[h * 40 + kc * 8 + pos] = packbf(w1[h * PCH + k], w1[h * PCH + k + 1]);
    }
    // w2: 16 rows x 64 pairs (stride 72 u32, base 5120)
    for (int i = t; i < 16 * 64; i += gridDim.x * 256) {
        int o = i >> 6, pr = i & 63;
        int kc = pr >> 3, p = pr & 7;
        int pos = (p < 4) ? 2 * p : 2 * (p - 4) + 1;
        int k = 16 * kc + 2 * p;
        g_wimg[5120 + o * 72 + kc * 8 + pos] = packbf(w2[o * HID + k], w2[o * HID + k + 1]);
    }
}

extern __shared__ char smc[];

__global__ __launch_bounds__(256, 4)
void nca_mma_kernel(const float* __restrict__ grid,
                    const float* __restrict__ noise,
                    const float* __restrict__ b1,
                    const float* __restrict__ b2,
                    float* __restrict__ out)
{
    const int tid = threadIdx.x;
    const int x0 = blockIdx.x * 128;
    const int y = blockIdx.y;
    const int b = blockIdx.z;

    // ---- stage weights via cp.async (overlaps with perception below) ----
    {
        const char* gsrc = (const char*)g_wimg;
        uint32_t sdst = smem_u32(smc + W1_B);
        #pragma unroll
        for (int j = 0; j < 7; j++) {
            int i = tid + 256 * j;
            if (i < (WIMG_U32 * 4) / 16)
                cp16(sdst + i * 16, gsrc + i * 16);
        }
        asm volatile("cp.async.commit_group;" ::: "memory");
    }
    if (tid < HID) ((float*)(smc + B1_B))[tid] = b1[tid];
    if (tid < TC)  ((float*)(smc + B2_B))[tid] = b2[tid];

    // ---- perception: 2 threads per pixel (channel split 8+8) ----
    {
        const int px = tid & 127;           // pixel within tile
        const int cb = (tid >> 7) << 3;     // channel base: 0 or 8
        const int x = x0 + px;
        const int pix = y * IMW + x;
        const bool ym = (y > 0), yp = (y < IMH - 1);
        const bool xm = (x > 0), xp = (x < IMW - 1);
        const float* gb = grid + ((size_t)b * TC + cb) * HW;

        float v[24];
        #pragma unroll
        for (int cc = 0; cc < 8; cc++) {
            const float* g = gb + cc * HW + pix;
            float n00 = (ym && xm) ? __ldg(g - IMW - 1) : 0.f;
            float n01 = (ym)       ? __ldg(g - IMW)     : 0.f;
            float n02 = (ym && xp) ? __ldg(g - IMW + 1) : 0.f;
            float n10 = (xm)       ? __ldg(g - 1)       : 0.f;
            float n11 =              __ldg(g);
            float n12 = (xp)       ? __ldg(g + 1)       : 0.f;
            float n20 = (yp && xm) ? __ldg(g + IMW - 1) : 0.f;
            float n21 = (yp)       ? __ldg(g + IMW)     : 0.f;
            float n22 = (yp && xp) ? __ldg(g + IMW + 1) : 0.f;
            // sobel_x faithful to reference: [[1,0,1],[2,0,-2],[1,0,-1]]/8
            float sx = (n00 + n02 + 2.f*n10 - 2.f*n12 + n20 - n22) * 0.125f;
            // sobel_y: [[1,2,1],[0,0,0],[-1,-2,-1]]/8
            float sy = (n00 + 2.f*n01 + n02 - n20 - 2.f*n21 - n22) * 0.125f;
            v[3*cc]     = n11;
            v[3*cc + 1] = sx;
            v[3*cc + 2] = sy;
        }
        uint32_t pw[12];
        #pragma unroll
        for (int m = 0; m < 12; m++) pw[m] = packbf(v[2*m], v[2*m + 1]);

        // pi-permuted store: per 16-k chunk, positions [p0,p4,p1,p5,p2,p6,p3,p7]
        uint32_t* prow = (uint32_t*)(smc + PERC_B + px * 160);
        if (cb == 0) {
            // chunk0 full (pairs 0-7), chunk1 pairs 0-3 (even positions)
            ((uint4*)prow)[0] = make_uint4(pw[0], pw[4], pw[1], pw[5]);
            ((uint4*)prow)[1] = make_uint4(pw[2], pw[6], pw[3], pw[7]);
            prow[8]  = pw[8];  prow[10] = pw[9];
            prow[12] = pw[10]; prow[14] = pw[11];
        } else {
            // chunk1 pairs 4-7 (odd positions), chunk2 full (pairs 0-7)
            prow[9]  = pw[0];  prow[11] = pw[1];
            prow[13] = pw[2];  prow[15] = pw[3];
            ((uint4*)prow)[4] = make_uint4(pw[4], pw[8], pw[5], pw[9]);
            ((uint4*)prow)[5] = make_uint4(pw[6], pw[10], pw[7], pw[11]);
        }
    }
    asm volatile("cp.async.wait_group 0;" ::: "memory");
    __syncthreads();

    // ---- per-warp GEMMs on one 16-pixel M tile ----
    const int l = tid & 31, wp = tid >> 5;
    const int g = l >> 2, cq = l & 3;
    const int P0 = wp * 16;

    // A1 fragments: uint2 = (a0,a2) / (a1,a3) per kc  (LDS.64, conflict-free)
    uint32_t a1[3][4];
    {
        const char* pb = smc + PERC_B + (P0 + g) * 160 + cq * 8;
        #pragma unroll
        for (int kc = 0; kc < 3; kc++) {
            uint2 lo = *(const uint2*)(pb + kc * 32);
            uint2 hi = *(const uint2*)(pb + kc * 32 + 8 * 160);
            a1[kc][0] = lo.x;  a1[kc][2] = lo.y;   // (g,   k=2q / k=2q+8)
            a1[kc][1] = hi.x;  a1[kc][3] = hi.y;   // (g+8, k=2q / k=2q+8)
        }
    }

    const char* w1c = smc + W1_B + g * 160 + cq * 8;
    const char* w2c = smc + W2_B + g * 288 + cq * 8;
    const float* b1s = (const float*)(smc + B1_B);

    float acc[2][4] = {};

    #pragma unroll
    for (int n0 = 0; n0 < 4; n0++) {         // hid chunk of 32
        const int H0 = 32 * n0;
        float d[4][4] = {};
        // GEMM1: kc outer, nt inner (4 independent d-chains); B via LDS.64
        #pragma unroll
        for (int kc = 0; kc < 3; kc++) {
            #pragma unroll
            for (int nt = 0; nt < 4; nt++) {
                const uint2 bv = *(const uint2*)(w1c + (H0 + 8*nt) * 160 + kc * 32);
                mma16(d[nt], a1[kc], bv.x, bv.y);
            }
        }
        // bias + relu + bf16 pack: D1 frag -> A2 frag directly.
        #pragma unroll
        for (int half = 0; half < 2; half++) {
            const int ntA = 2 * half, ntB = ntA + 1;
            const float bA0 = b1s[H0 + 8*ntA + 2*cq];
            const float bA1 = b1s[H0 + 8*ntA + 2*cq + 1];
            const float bB0 = b1s[H0 + 8*ntB + 2*cq];
            const float bB1 = b1s[H0 + 8*ntB + 2*cq + 1];
            uint32_t a2[4];
            a2[0] = packbf(fmaxf(d[ntA][0] + bA0, 0.f),
                           fmaxf(d[ntA][1] + bA1, 0.f));   // (g,   k=2q,2q+1)
            a2[1] = packbf(fmaxf(d[ntA][2] + bA0, 0.f),
                           fmaxf(d[ntA][3] + bA1, 0.f));   // (g+8, k=2q,2q+1)
            a2[2] = packbf(fmaxf(d[ntB][0] + bB0, 0.f),
                           fmaxf(d[ntB][1] + bB1, 0.f));   // (g,   k=2q+8,+9)
            a2[3] = packbf(fmaxf(d[ntB][2] + bB0, 0.f),
                           fmaxf(d[ntB][3] + bB1, 0.f));   // (g+8, k=2q+8,+9)
            const int kb2 = (H0 + 16 * half) * 2;          // chunk byte offset
            #pragma unroll
            for (int nt2 = 0; nt2 < 2; nt2++) {
                const uint2 bv = *(const uint2*)(w2c + nt2 * (8 * 288) + kb2);
                mma16(acc[nt2], a2, bv.x, bv.y);
            }
        }
    }

    // ---- epilogue: +b2, mask, exact-f32 residual, clip, store ----
    const float* b2s = (const float*)(smc + B2_B);
    const float* nb = noise + (size_t)b * HW + y * IMW + x0;
    const int r0 = P0 + g;
    const float m0 = (__ldg(nb + r0)     < 0.5f) ? 1.f : 0.f;
    const float m1 = (__ldg(nb + r0 + 8) < 0.5f) ? 1.f : 0.f;
    #pragma unroll
    for (int nt2 = 0; nt2 < 2; nt2++) {
        const int o0 = 8*nt2 + 2*cq;
        const float bv0 = b2s[o0];
        const float bv1 = b2s[o0 + 1];
        const float* gp0 = grid + ((size_t)b * TC + o0) * HW + y * IMW + x0;
        const float* gp1 = gp0 + HW;
        float* op0 = out + ((size_t)b * TC + o0) * HW + y * IMW + x0;
        float* op1 = op0 + HW;
        float v;
        v = fmaf(acc[nt2][0] + bv0, m0, __ldg(gp0 + r0));
        op0[r0]     = fminf(fmaxf(v, -2.f), 2.f);
        v = fmaf(acc[nt2][1] + bv1, m0, __ldg(gp1 + r0));
        op1[r0]     = fminf(fmaxf(v, -2.f), 2.f);
        v = fmaf(acc[nt2][2] + bv0, m1, __ldg(gp0 + r0 + 8));
        op0[r0 + 8] = fminf(fmaxf(v, -2.f), 2.f);
        v = fmaf(acc[nt2][3] + bv1, m1, __ldg(gp1 + r0 + 8));
        op1[r0 + 8] = fminf(fmaxf(v, -2.f), 2.f);
    }
}

extern "C" void kernel_launch(void* const* d_in, const int* in_sizes, int n_in,
                              void* d_out, int out_size)
{
    const float* grid  = (const float*)d_in[0];
    const float* noise = (const float*)d_in[1];
    const float* w1    = (const float*)d_in[2];
    const float* b1    = (const float*)d_in[3];
    const float* w2    = (const float*)d_in[4];
    const float* b2    = (const float*)d_in[5];
    float* out = (float*)d_out;

    prep_kernel<<<8, 256>>>(w1, w2);

    cudaFuncSetAttribute(nca_mma_kernel,
                         cudaFuncAttributeMaxDynamicSharedMemorySize, SMEM_BYTES);
    dim3 block(256, 1, 1);
    dim3 grd(IMW / 128, IMH, 32);
    nca_mma_kernel<<<grd, block, SMEM_BYTES>>>(grid, noise, b1, b2, out);
}